// round 1
// baseline (speedup 1.0000x reference)
#include <cuda_runtime.h>
#include <cuda_fp16.h>
#include <cstdint>

#define INPUTDIM 512
#define DEG 8
#define OUTDIM 64
#define KDIM (INPUTDIM * DEG)   // 4096

// ---------------- scratch (static device globals; no allocation) ----------------
__device__ __half   d_Bh[KDIM * OUTDIM];   // repacked coeffs [k=i*8+d][o], fp16 (512 KB)
__device__ unsigned d_minu, d_maxu;
__device__ float2   d_ab;                  // xn = a*x + b

// ---------------- float <-> order-preserving uint ----------------
__device__ __forceinline__ unsigned f2ord(float f) {
    unsigned u = __float_as_uint(f);
    return (u & 0x80000000u) ? ~u : (u | 0x80000000u);
}
__device__ __forceinline__ float ord2f(unsigned u) {
    unsigned b = (u & 0x80000000u) ? (u ^ 0x80000000u) : ~u;
    return __uint_as_float(b);
}

// ---------------- kernel 1: reset ----------------
__global__ void k_init() {
    d_minu = 0xFFFFFFFFu;
    d_maxu = 0u;
}

// ---------------- kernel 2: global min/max ----------------
__global__ void k_minmax(const float4* __restrict__ x, int n4) {
    float lmin =  3.4e38f, lmax = -3.4e38f;
    int stride = gridDim.x * blockDim.x;
    for (int idx = blockIdx.x * blockDim.x + threadIdx.x; idx < n4; idx += stride) {
        float4 v = x[idx];
        lmin = fminf(lmin, fminf(fminf(v.x, v.y), fminf(v.z, v.w)));
        lmax = fmaxf(lmax, fmaxf(fmaxf(v.x, v.y), fmaxf(v.z, v.w)));
    }
    #pragma unroll
    for (int o = 16; o; o >>= 1) {
        lmin = fminf(lmin, __shfl_xor_sync(0xFFFFFFFFu, lmin, o));
        lmax = fmaxf(lmax, __shfl_xor_sync(0xFFFFFFFFu, lmax, o));
    }
    __shared__ float smin[8], smax[8];
    int w = threadIdx.x >> 5;
    if ((threadIdx.x & 31) == 0) { smin[w] = lmin; smax[w] = lmax; }
    __syncthreads();
    if (threadIdx.x == 0) {
        int nw = blockDim.x >> 5;
        for (int i = 1; i < nw; i++) {
            lmin = fminf(lmin, smin[i]);
            lmax = fmaxf(lmax, smax[i]);
        }
        atomicMin(&d_minu, f2ord(lmin));
        atomicMax(&d_maxu, f2ord(lmax));
    }
}

// ---------------- kernel 3a: normalization constants ----------------
__global__ void k_scale() {
    float mn = ord2f(d_minu), mx = ord2f(d_maxu);
    float a = 2.0f / (mx - mn);
    d_ab = make_float2(a, -a * mn - 1.0f);
}

// ---------------- kernel 3b: repack coeffs [O][I][D] -> fp16 [K=I*8+D][O] ----------------
__global__ void k_prepB(const float* __restrict__ coeffs) {
    int idx = blockIdx.x * blockDim.x + threadIdx.x;
    int stride = gridDim.x * blockDim.x;
    for (; idx < KDIM * OUTDIM; idx += stride) {
        int k = idx >> 6, o = idx & 63;
        int i = k >> 3, d = k & 7;
        d_Bh[idx] = __float2half(coeffs[(o * INPUTDIM + i) * DEG + d]);
    }
}

// ---------------- PTX helpers ----------------
__device__ __forceinline__ void ldsm_x4(unsigned* r, unsigned addr) {
    asm volatile("ldmatrix.sync.aligned.m8n8.x4.shared.b16 {%0,%1,%2,%3}, [%4];\n"
                 : "=r"(r[0]), "=r"(r[1]), "=r"(r[2]), "=r"(r[3]) : "r"(addr));
}
__device__ __forceinline__ void ldsm_x4_trans(unsigned* r, unsigned addr) {
    asm volatile("ldmatrix.sync.aligned.m8n8.x4.trans.shared.b16 {%0,%1,%2,%3}, [%4];\n"
                 : "=r"(r[0]), "=r"(r[1]), "=r"(r[2]), "=r"(r[3]) : "r"(addr));
}
__device__ __forceinline__ void mma16816(float* c, const unsigned* a, unsigned b0, unsigned b1) {
    asm volatile(
        "mma.sync.aligned.m16n8k16.row.col.f32.f16.f16.f32 "
        "{%0,%1,%2,%3}, {%4,%5,%6,%7}, {%8,%9}, {%0,%1,%2,%3};\n"
        : "+f"(c[0]), "+f"(c[1]), "+f"(c[2]), "+f"(c[3])
        : "r"(a[0]), "r"(a[1]), "r"(a[2]), "r"(a[3]), "r"(b0), "r"(b1));
}

// ---------------- kernel 4: fused Legendre + GEMM ----------------
#define BM 128
#define IC 8                    // i's per stage
#define KC (IC * DEG)           // 64 k's per stage
#define A_STRIDE 144            // bytes per A row (128 data + 16 pad, conflict-free)
#define B_STRIDE 144
#define NSTAGES (INPUTDIM / IC) // 64

__global__ __launch_bounds__(256) void k_main(const float* __restrict__ x,
                                              const float* __restrict__ bias,
                                              float* __restrict__ out) {
    __shared__ __align__(16) unsigned char As[BM * A_STRIDE];  // 18432 B
    __shared__ __align__(16) unsigned char Bs[KC * B_STRIDE];  //  9216 B

    const int tid  = threadIdx.x;
    const int warp = tid >> 5, lane = tid & 31;
    const int n0   = blockIdx.x * BM;
    const float2 ab = d_ab;

    float acc[8][4];
    #pragma unroll
    for (int i = 0; i < 8; i++)
        #pragma unroll
        for (int j = 0; j < 4; j++) acc[i][j] = 0.f;

    // A-producer mapping: thread -> (row, half of 8 i's)
    const int arow  = tid >> 1;          // 0..127
    const int ihalf = tid & 1;           // 0/1 -> i offset 0 or 4
    const float* xrow = x + (size_t)(n0 + arow) * INPUTDIM + ihalf * 4;
    // B-producer mapping: 4 threads x 32B per k-row
    const int brow = tid >> 2;           // 0..63
    const int bq   = (tid & 3) * 16;     // offset in halfs

    // ldmatrix source addresses (computed once)
    const unsigned a_base = (unsigned)__cvta_generic_to_shared(As)
                          + (warp * 16 + (lane & 15)) * A_STRIDE + ((lane >> 4) & 1) * 16;
    const unsigned b_base = (unsigned)__cvta_generic_to_shared(Bs)
                          + (lane & 15) * B_STRIDE + ((lane >> 4) & 1) * 16;

    for (int s = 0; s < NSTAGES; s++) {
        const int i0 = s * IC;

        // ---- produce A: load 4 x's, Legendre recurrence in fp32, store 32 fp16 ----
        float4 xv = *(const float4*)(xrow + i0);
        float xs[4] = {xv.x, xv.y, xv.z, xv.w};
        __align__(16) __half2 pk[16];
        #pragma unroll
        for (int q = 0; q < 4; q++) {
            float t = fmaf(ab.x, xs[q], ab.y);
            float P[8];
            P[0] = 1.f; P[1] = t;
            #pragma unroll
            for (int nr = 2; nr < 8; nr++)
                P[nr] = ((2.f * nr - 1.f) * t * P[nr - 1] - (nr - 1.f) * P[nr - 2]) * (1.f / nr);
            #pragma unroll
            for (int dd = 0; dd < 4; dd++)
                pk[q * 4 + dd] = __floats2half2_rn(P[2 * dd], P[2 * dd + 1]);
        }
        uint4* adst = (uint4*)(As + arow * A_STRIDE + ihalf * 64);
        #pragma unroll
        for (int q = 0; q < 4; q++) adst[q] = *(uint4*)(&pk[q * 4]);

        // ---- stage B chunk (L2-hot): 64 k-rows x 64 o fp16 ----
        {
            const __half* bsrc = d_Bh + (size_t)(i0 * DEG + brow) * OUTDIM + bq;
            uint4 v0 = *(const uint4*)(bsrc);
            uint4 v1 = *(const uint4*)(bsrc + 8);
            uint4* bdst = (uint4*)(Bs + brow * B_STRIDE + bq * 2);
            bdst[0] = v0; bdst[1] = v1;
        }
        __syncthreads();

        // ---- MMA: each warp m16 x n64, K=64 chunk ----
        #pragma unroll
        for (int kk = 0; kk < 4; kk++) {
            unsigned a[4];
            ldsm_x4(a, a_base + kk * 32);
            #pragma unroll
            for (int j = 0; j < 4; j++) {
                unsigned b[4];
                ldsm_x4_trans(b, b_base + kk * 16 * B_STRIDE + j * 32);
                mma16816(acc[2 * j],     a, b[0], b[1]);
                mma16816(acc[2 * j + 1], a, b[2], b[3]);
            }
        }
        __syncthreads();
    }

    // ---- epilogue: add bias, write fp32 ----
    const int g = lane >> 2, t4 = lane & 3;
    const int row0 = n0 + warp * 16 + g;
    #pragma unroll
    for (int nt = 0; nt < 8; nt++) {
        int col = nt * 8 + 2 * t4;
        float b0 = bias[col], b1 = bias[col + 1];
        *(float2*)(out + (size_t)row0 * OUTDIM + col) =
            make_float2(acc[nt][0] + b0, acc[nt][1] + b1);
        *(float2*)(out + (size_t)(row0 + 8) * OUTDIM + col) =
            make_float2(acc[nt][2] + b0, acc[nt][3] + b1);
    }
}

// ---------------- launch ----------------
extern "C" void kernel_launch(void* const* d_in, const int* in_sizes, int n_in,
                              void* d_out, int out_size) {
    const float* x      = (const float*)d_in[0];
    const float* coeffs = (const float*)d_in[1];
    const float* bias   = (const float*)d_in[2];
    float* out = (float*)d_out;

    const int nx = in_sizes[0];            // 33554432
    const int Nrows = nx / INPUTDIM;       // 65536

    k_init<<<1, 1>>>();
    k_minmax<<<1024, 256>>>((const float4*)x, nx / 4);
    k_scale<<<1, 1>>>();
    k_prepB<<<256, 256>>>(coeffs);
    k_main<<<Nrows / BM, 256>>>(x, bias, out);
}

// round 3
// speedup vs baseline: 1.0003x; 1.0003x over previous
#include <cuda_runtime.h>
#include <cuda_fp16.h>
#include <cstdint>

#define INPUTDIM 512
#define DEG 8
#define OUTDIM 64
#define KDIM (INPUTDIM * DEG)   // 4096

// ---------------- scratch (static device globals; no allocation) ----------------
__device__ __half   d_Bh[KDIM * OUTDIM];   // repacked coeffs [k=i*8+d][o], fp16
__device__ unsigned d_minu, d_maxu;
__device__ float2   d_ab;                  // xn = a*x + b

// ---------------- float <-> order-preserving uint ----------------
__device__ __forceinline__ unsigned f2ord(float f) {
    unsigned u = __float_as_uint(f);
    return (u & 0x80000000u) ? ~u : (u | 0x80000000u);
}
__device__ __forceinline__ float ord2f(unsigned u) {
    unsigned b = (u & 0x80000000u) ? (u ^ 0x80000000u) : ~u;
    return __uint_as_float(b);
}

// ---------------- kernel 1: reset ----------------
__global__ void k_init() {
    d_minu = 0xFFFFFFFFu;
    d_maxu = 0u;
}

// ---------------- kernel 2: global min/max ----------------
__global__ void k_minmax(const float4* __restrict__ x, int n4) {
    float lmin =  3.4e38f, lmax = -3.4e38f;
    int stride = gridDim.x * blockDim.x;
    for (int idx = blockIdx.x * blockDim.x + threadIdx.x; idx < n4; idx += stride) {
        float4 v = x[idx];
        lmin = fminf(lmin, fminf(fminf(v.x, v.y), fminf(v.z, v.w)));
        lmax = fmaxf(lmax, fmaxf(fmaxf(v.x, v.y), fmaxf(v.z, v.w)));
    }
    #pragma unroll
    for (int o = 16; o; o >>= 1) {
        lmin = fminf(lmin, __shfl_xor_sync(0xFFFFFFFFu, lmin, o));
        lmax = fmaxf(lmax, __shfl_xor_sync(0xFFFFFFFFu, lmax, o));
    }
    __shared__ float smin[8], smax[8];
    int w = threadIdx.x >> 5;
    if ((threadIdx.x & 31) == 0) { smin[w] = lmin; smax[w] = lmax; }
    __syncthreads();
    if (threadIdx.x == 0) {
        int nw = blockDim.x >> 5;
        for (int i = 1; i < nw; i++) {
            lmin = fminf(lmin, smin[i]);
            lmax = fmaxf(lmax, smax[i]);
        }
        atomicMin(&d_minu, f2ord(lmin));
        atomicMax(&d_maxu, f2ord(lmax));
    }
}

// ---------------- kernel 3a: normalization constants ----------------
__global__ void k_scale() {
    float mn = ord2f(d_minu), mx = ord2f(d_maxu);
    float a = 2.0f / (mx - mn);
    d_ab = make_float2(a, -a * mn - 1.0f);
}

// ---------------- kernel 3b: repack coeffs [O][I][D] -> fp16 [K=I*8+D][O] ----------------
__global__ void k_prepB(const float* __restrict__ coeffs) {
    int idx = blockIdx.x * blockDim.x + threadIdx.x;
    int stride = gridDim.x * blockDim.x;
    for (; idx < KDIM * OUTDIM; idx += stride) {
        int k = idx >> 6, o = idx & 63;
        int i = k >> 3, d = k & 7;
        d_Bh[idx] = __float2half(coeffs[(o * INPUTDIM + i) * DEG + d]);
    }
}

// ---------------- PTX helpers (sm_80-class only: legal in compute_103 PTX) ----------------
__device__ __forceinline__ void ldsm_x4(unsigned* r, unsigned addr) {
    asm volatile("ldmatrix.sync.aligned.m8n8.x4.shared.b16 {%0,%1,%2,%3}, [%4];\n"
                 : "=r"(r[0]), "=r"(r[1]), "=r"(r[2]), "=r"(r[3]) : "r"(addr));
}
__device__ __forceinline__ void ldsm_x4_trans(unsigned* r, unsigned addr) {
    asm volatile("ldmatrix.sync.aligned.m8n8.x4.trans.shared.b16 {%0,%1,%2,%3}, [%4];\n"
                 : "=r"(r[0]), "=r"(r[1]), "=r"(r[2]), "=r"(r[3]) : "r"(addr));
}
__device__ __forceinline__ void mma16816(float* c, const unsigned* a, unsigned b0, unsigned b1) {
    asm volatile(
        "mma.sync.aligned.m16n8k16.row.col.f32.f16.f16.f32 "
        "{%0,%1,%2,%3}, {%4,%5,%6,%7}, {%8,%9}, {%0,%1,%2,%3};\n"
        : "+f"(c[0]), "+f"(c[1]), "+f"(c[2]), "+f"(c[3])
        : "r"(a[0]), "r"(a[1]), "r"(a[2]), "r"(a[3]), "r"(b0), "r"(b1));
}
__device__ __forceinline__ void cp_async16(uint32_t dst, const void* src) {
    asm volatile("cp.async.cg.shared.global [%0], [%1], 16;" :: "r"(dst), "l"(src));
}
#define CP_COMMIT()  asm volatile("cp.async.commit_group;" ::: "memory")
#define CP_WAIT(n)   asm volatile("cp.async.wait_group %0;" :: "n"(n) : "memory")

// ---------------- kernel 4: fused Legendre + GEMM (3-stage pipeline) ----------------
#define BM 128
#define IC 8                    // i's per stage
#define KC (IC * DEG)           // 64 k's per stage
#define A_STRIDE 144            // bytes per A row (128 data + 16 pad, conflict-free)
#define B_STRIDE 144
#define NSTAGES (INPUTDIM / IC) // 64
#define A_BYTES (BM * A_STRIDE)         // 18432
#define B_BYTES (KC * B_STRIDE)         //  9216
#define BUF_STRIDE (A_BYTES + B_BYTES)  // 27648
#define SMEM_BYTES (3 * BUF_STRIDE)     // 82944

__global__ __launch_bounds__(256, 2) void k_main(const float* __restrict__ x,
                                                 const float* __restrict__ bias,
                                                 float* __restrict__ out) {
    extern __shared__ __align__(128) unsigned char sm[];
    __shared__ float sbias[OUTDIM];

    const uint32_t smem_u32 = (uint32_t)__cvta_generic_to_shared(sm);
    const int tid  = threadIdx.x;
    const int warp = tid >> 5, lane = tid & 31;
    const int n0   = blockIdx.x * BM;
    const float2 ab = d_ab;

    if (tid < OUTDIM) sbias[tid] = bias[tid];

    float acc[8][4];
    #pragma unroll
    for (int i = 0; i < 8; i++)
        #pragma unroll
        for (int j = 0; j < 4; j++) acc[i][j] = 0.f;

    // producer mappings
    const int arow  = tid >> 1;                 // 0..127
    const int ihalf = tid & 1;                  // which 4 of the 8 i's
    const float* xrow = x + (size_t)(n0 + arow) * INPUTDIM + ihalf * 4;
    const uint32_t a_sts = arow * A_STRIDE + ihalf * 64;           // within A region
    const int brow = tid >> 2;                  // 0..63 (k-row)
    const int bq   = tid & 3;                   // 32B quarter of the 128B row
    const __half* bsrc0 = d_Bh + (size_t)brow * OUTDIM + bq * 16;  // + s*KC*OUTDIM
    const uint32_t b_sts = A_BYTES + brow * B_STRIDE + bq * 32;    // within buffer

    // ldsm consumer bases (buffer 0)
    const uint32_t a_ld0 = smem_u32 + (warp * 16 + (lane & 15)) * A_STRIDE + ((lane >> 4) & 1) * 16;
    const uint32_t b_ld0 = smem_u32 + A_BYTES + (lane & 15) * B_STRIDE + ((lane >> 4) & 1) * 16;

    // ---- Legendre producer: compute+store basis for stage s into buffer `buf` ----
    auto produce_A = [&](int buf, float4 xv) {
        float xs[4] = {xv.x, xv.y, xv.z, xv.w};
        __align__(16) __half2 pk[16];
        #pragma unroll
        for (int q = 0; q < 4; q++) {
            float t = fmaf(ab.x, xs[q], ab.y);
            float P[8];
            P[0] = 1.f; P[1] = t;
            #pragma unroll
            for (int nr = 2; nr < 8; nr++)
                P[nr] = ((2.f * nr - 1.f) * t * P[nr - 1] - (nr - 1.f) * P[nr - 2]) * (1.f / nr);
            #pragma unroll
            for (int dd = 0; dd < 4; dd++)
                pk[q * 4 + dd] = __floats2half2_rn(P[2 * dd], P[2 * dd + 1]);
        }
        unsigned char* adst = sm + buf * BUF_STRIDE + a_sts;
        #pragma unroll
        for (int q = 0; q < 4; q++)
            *(uint4*)(adst + q * 16) = *(uint4*)(&pk[q * 4]);
    };
    auto produce_B = [&](int buf, int s) {
        const __half* src = bsrc0 + (size_t)s * KC * OUTDIM;
        uint32_t dst = smem_u32 + buf * BUF_STRIDE + b_sts;
        cp_async16(dst, src);
        cp_async16(dst + 16, src + 8);
        CP_COMMIT();
    };

    // ---- prologue: fill stage 0, prefetch x(1) ----
    produce_B(0, 0);
    produce_A(0, *(const float4*)(xrow));
    float4 xr = *(const float4*)(xrow + IC);

    int cur = 0;
    for (int s = 0; s < NSTAGES; s++) {
        const int nxt = (cur == 2) ? 0 : cur + 1;

        // produce stage s+1 (B via cp.async, A via registers), prefetch x(s+2)
        if (s < NSTAGES - 1) {
            produce_B(nxt, s + 1);
            produce_A(nxt, xr);
            if (s < NSTAGES - 2) xr = *(const float4*)(xrow + (s + 2) * IC);
            CP_WAIT(1);               // B(s) landed; B(s+1) may stay in flight
        } else {
            CP_WAIT(0);
        }
        __syncthreads();              // publish stage s to all warps

        // ---- consume stage s: each warp m16 x n64, K=64 ----
        const uint32_t a_ld = a_ld0 + cur * BUF_STRIDE;
        const uint32_t b_ld = b_ld0 + cur * BUF_STRIDE;
        #pragma unroll
        for (int kk = 0; kk < 4; kk++) {
            unsigned a[4];
            ldsm_x4(a, a_ld + kk * 32);
            #pragma unroll
            for (int j = 0; j < 4; j++) {
                unsigned b[4];
                ldsm_x4_trans(b, b_ld + kk * 16 * B_STRIDE + j * 32);
                mma16816(acc[2 * j],     a, b[0], b[1]);
                mma16816(acc[2 * j + 1], a, b[2], b[3]);
            }
        }
        cur = nxt;
    }

    // ---- epilogue: add bias, write fp32 ----
    const int g = lane >> 2, t4 = lane & 3;
    const int row0 = n0 + warp * 16 + g;
    #pragma unroll
    for (int nt = 0; nt < 8; nt++) {
        int col = nt * 8 + 2 * t4;
        float b0 = sbias[col], b1 = sbias[col + 1];
        *(float2*)(out + (size_t)row0 * OUTDIM + col) =
            make_float2(acc[nt][0] + b0, acc[nt][1] + b1);
        *(float2*)(out + (size_t)(row0 + 8) * OUTDIM + col) =
            make_float2(acc[nt][2] + b0, acc[nt][3] + b1);
    }
}

// ---------------- launch ----------------
extern "C" void kernel_launch(void* const* d_in, const int* in_sizes, int n_in,
                              void* d_out, int out_size) {
    const float* x      = (const float*)d_in[0];
    const float* coeffs = (const float*)d_in[1];
    const float* bias   = (const float*)d_in[2];
    float* out = (float*)d_out;

    const int nx = in_sizes[0];            // 33554432
    const int Nrows = nx / INPUTDIM;       // 65536

    cudaFuncSetAttribute(k_main, cudaFuncAttributeMaxDynamicSharedMemorySize, SMEM_BYTES);

    k_init<<<1, 1>>>();
    k_minmax<<<2048, 256>>>((const float4*)x, nx / 4);
    k_scale<<<1, 1>>>();
    k_prepB<<<256, 256>>>(coeffs);
    k_main<<<Nrows / BM, 256, SMEM_BYTES>>>(x, bias, out);
}